// round 2
// baseline (speedup 1.0000x reference)
#include <cuda_runtime.h>
#include <math.h>

#define NN 50000
#define EE 1600000
#define E2T (EE + NN)
#define GG 512

// ---------------- scratch (allocation-free: __device__ globals) ----------------
__device__ float    g_xl1[NN * 100];
__device__ float    g_xr1[NN * 100];
__device__ float    g_out1[NN * 100];
__device__ float    g_xl2[NN * 200];
__device__ float    g_xr2[NN * 200];
__device__ float    g_out2[NN * 200];
__device__ float    g_h3[NN * 400];
__device__ float    g_s[E2T];
__device__ unsigned g_m[NN];
__device__ float    g_z[NN];
__device__ float    g_deg[NN];
__device__ float    g_easum[NN * 18];
__device__ float    g_pool[GG * 400];
__device__ float    g_cnt[GG];
__device__ float    g_y1[GG * 200];
__device__ float    g_y2[GG * 100];

// monotonic float <-> uint map for atomicMax on floats (handles negatives)
__device__ __forceinline__ unsigned fmap(float f) {
    unsigned u = __float_as_uint(f);
    return (u & 0x80000000u) ? ~u : (u | 0x80000000u);
}
__device__ __forceinline__ float funmap(unsigned u) {
    return __uint_as_float((u & 0x80000000u) ? (u & 0x7FFFFFFFu) : ~u);
}

// ---------------- self-loop edge-attr accumulation ----------------
__global__ void k_ea_accum(const int* __restrict__ ei, const float* __restrict__ ea,
                           float* __restrict__ deg, float* __restrict__ easum) {
    int i = blockIdx.x * blockDim.x + threadIdx.x;
    if (i >= EE * 18) return;
    int e = i / 18, k = i - e * 18;
    int d = ei[EE + e];
    atomicAdd(&easum[d * 18 + k], ea[i]);
    if (k == 0) atomicAdd(&deg[d], 1.0f);
}

// ---------------- generic row-tiled linear: y = [relu](x @ W + b) ----------------
__global__ void k_linear(const float* __restrict__ x, const float* __restrict__ W,
                         const float* __restrict__ b, float* __restrict__ y,
                         int nrows, int cin, int cout, int do_relu) {
    extern __shared__ float xs[];  // [4][cin]
    int base = blockIdx.x * 4;
    for (int idx = threadIdx.x; idx < 4 * cin; idx += blockDim.x) {
        int r = idx / cin, k = idx - r * cin;
        xs[idx] = (base + r < nrows) ? x[(base + r) * cin + k] : 0.f;
    }
    __syncthreads();
    for (int c = threadIdx.x; c < cout; c += blockDim.x) {
        float a0 = 0.f, a1 = 0.f, a2 = 0.f, a3 = 0.f;
        const float* x0 = xs;
        const float* x1 = xs + cin;
        const float* x2 = xs + 2 * cin;
        const float* x3 = xs + 3 * cin;
        for (int k = 0; k < cin; k++) {
            float wv = W[k * cout + c];
            a0 += x0[k] * wv; a1 += x1[k] * wv; a2 += x2[k] * wv; a3 += x3[k] * wv;
        }
        float bb = b[c];
        a0 += bb; a1 += bb; a2 += bb; a3 += bb;
        if (do_relu) {
            a0 = fmaxf(a0, 0.f); a1 = fmaxf(a1, 0.f);
            a2 = fmaxf(a2, 0.f); a3 = fmaxf(a3, 0.f);
        }
        if (base + 0 < nrows) y[(base + 0) * cout + c] = a0;
        if (base + 1 < nrows) y[(base + 1) * cout + c] = a1;
        if (base + 2 < nrows) y[(base + 2) * cout + c] = a2;
        if (base + 3 < nrows) y[(base + 3) * cout + c] = a3;
    }
}

// ---------------- GATv2 edge score: one warp per edge ----------------
// s_e = a . leaky_relu(xl[src] + xr[dst] + ea_e @ We, 0.2); atomicMax m[dst]
__global__ void k_score(const int* __restrict__ ei, const float* __restrict__ ea,
                        const float* __restrict__ easum, const float* __restrict__ deg,
                        const float* __restrict__ We, const float* __restrict__ av,
                        const float* __restrict__ xl, const float* __restrict__ xr,
                        float* __restrict__ s, unsigned* __restrict__ m, int C) {
    int e = (blockIdx.x * blockDim.x + threadIdx.x) >> 5;
    int lane = threadIdx.x & 31;
    if (e >= E2T) return;
    int sn, dn;
    float eav = 0.f;
    if (e < EE) {
        sn = ei[e]; dn = ei[EE + e];
        if (lane < 18) eav = ea[e * 18 + lane];
    } else {
        int n = e - EE; sn = n; dn = n;
        if (lane < 18) eav = easum[n * 18 + lane] / fmaxf(deg[n], 1.0f);
    }
    // Broadcast the 18 edge-attr values to ALL lanes while the warp is fully
    // converged (shuffles inside the strided c-loop were UB: trailing
    // iterations are lane-divergent for C % 32 != 0).
    float eaw[18];
#pragma unroll
    for (int k = 0; k < 18; k++) eaw[k] = __shfl_sync(0xffffffffu, eav, k);

    float acc = 0.f;
    for (int c = lane; c < C; c += 32) {
        float v = xl[sn * C + c] + xr[dn * C + c];
#pragma unroll
        for (int k = 0; k < 18; k++)
            v += eaw[k] * We[k * C + c];
        v = (v > 0.f) ? v : 0.2f * v;
        acc += av[c] * v;
    }
    for (int o = 16; o; o >>= 1) acc += __shfl_down_sync(0xffffffffu, acc, o);
    if (lane == 0) {
        s[e] = acc;
        atomicMax(&m[dn], fmap(acc));
    }
}

// ---------------- exp + denominator ----------------
__global__ void k_expz(const int* __restrict__ ei, float* __restrict__ s,
                       const unsigned* __restrict__ m, float* __restrict__ z) {
    int e = blockIdx.x * blockDim.x + threadIdx.x;
    if (e >= E2T) return;
    int dn = (e < EE) ? ei[EE + e] : (e - EE);
    float ex = expf(s[e] - funmap(m[dn]));
    s[e] = ex;
    atomicAdd(&z[dn], ex);
}

// ---------------- weighted aggregation: one warp per edge ----------------
__global__ void k_agg(const int* __restrict__ ei, const float* __restrict__ s,
                      const float* __restrict__ z, const float* __restrict__ xl,
                      float* __restrict__ out, int C) {
    int e = (blockIdx.x * blockDim.x + threadIdx.x) >> 5;
    int lane = threadIdx.x & 31;
    if (e >= E2T) return;
    int sn, dn;
    if (e < EE) { sn = ei[e]; dn = ei[EE + e]; }
    else        { sn = e - EE; dn = sn; }
    float alpha = s[e] / z[dn];
    for (int c = lane; c < C; c += 32)
        atomicAdd(&out[dn * C + c], alpha * xl[sn * C + c]);
}

// ---------------- bias + relu epilogue ----------------
__global__ void k_bias_relu(float* __restrict__ h, const float* __restrict__ b,
                            int total, int C) {
    int i = blockIdx.x * blockDim.x + threadIdx.x;
    if (i >= total) return;
    h[i] = fmaxf(h[i] + b[i % C], 0.f);
}

// ---------------- mean pooling ----------------
__global__ void k_pool(const float* __restrict__ h3, const int* __restrict__ bid,
                       float* __restrict__ pool, float* __restrict__ cnt) {
    int i = blockIdx.x * blockDim.x + threadIdx.x;
    if (i >= NN * 400) return;
    int n = i / 400, c = i - n * 400;
    int g = bid[n];
    atomicAdd(&pool[g * 400 + c], h3[i]);
    if (c == 0) atomicAdd(&cnt[g], 1.0f);
}

__global__ void k_pooldiv(float* __restrict__ pool, const float* __restrict__ cnt) {
    int i = blockIdx.x * blockDim.x + threadIdx.x;
    if (i >= GG * 400) return;
    pool[i] /= fmaxf(cnt[i / 400], 1.0f);
}

// ---------------- launch ----------------
extern "C" void kernel_launch(void* const* d_in, const int* in_sizes, int n_in,
                              void* d_out, int out_size) {
    const float* x   = (const float*)d_in[0];
    const int*   ei  = (const int*)d_in[1];
    const float* ea  = (const float*)d_in[2];
    const int*   bid = (const int*)d_in[3];
    const float* W1l = (const float*)d_in[4];
    const float* b1l = (const float*)d_in[5];
    const float* W1r = (const float*)d_in[6];
    const float* b1r = (const float*)d_in[7];
    const float* W1e = (const float*)d_in[8];
    const float* a1  = (const float*)d_in[9];
    const float* c1  = (const float*)d_in[10];
    const float* W2l = (const float*)d_in[11];
    const float* b2l = (const float*)d_in[12];
    const float* W2r = (const float*)d_in[13];
    const float* b2r = (const float*)d_in[14];
    const float* W2e = (const float*)d_in[15];
    const float* a2  = (const float*)d_in[16];
    const float* c2  = (const float*)d_in[17];
    const float* W3  = (const float*)d_in[18];
    const float* b3  = (const float*)d_in[19];
    const float* F1  = (const float*)d_in[20];
    const float* bf1 = (const float*)d_in[21];
    const float* F2  = (const float*)d_in[22];
    const float* bf2 = (const float*)d_in[23];
    const float* F3  = (const float*)d_in[24];
    const float* bf3 = (const float*)d_in[25];

    float *xl1, *xr1, *out1, *xl2, *xr2, *out2, *h3, *s, *z, *deg, *easum, *pool, *cnt, *y1, *y2;
    unsigned* m;
    cudaGetSymbolAddress((void**)&xl1,  g_xl1);
    cudaGetSymbolAddress((void**)&xr1,  g_xr1);
    cudaGetSymbolAddress((void**)&out1, g_out1);
    cudaGetSymbolAddress((void**)&xl2,  g_xl2);
    cudaGetSymbolAddress((void**)&xr2,  g_xr2);
    cudaGetSymbolAddress((void**)&out2, g_out2);
    cudaGetSymbolAddress((void**)&h3,   g_h3);
    cudaGetSymbolAddress((void**)&s,    g_s);
    cudaGetSymbolAddress((void**)&m,    g_m);
    cudaGetSymbolAddress((void**)&z,    g_z);
    cudaGetSymbolAddress((void**)&deg,  g_deg);
    cudaGetSymbolAddress((void**)&easum,g_easum);
    cudaGetSymbolAddress((void**)&pool, g_pool);
    cudaGetSymbolAddress((void**)&cnt,  g_cnt);
    cudaGetSymbolAddress((void**)&y1,   g_y1);
    cudaGetSymbolAddress((void**)&y2,   g_y2);

    const int T = 256;
    const int edgeWarpGrid = (E2T + 7) / 8;  // 8 warps (256 threads) per block

    // --- self-loop attrs ---
    cudaMemsetAsync(deg, 0, NN * sizeof(float));
    cudaMemsetAsync(easum, 0, NN * 18 * sizeof(float));
    k_ea_accum<<<(EE * 18 + T - 1) / T, T>>>(ei, ea, deg, easum);

    // --- layer 1 (Cin=16 -> C=100) ---
    k_linear<<<(NN + 3) / 4, T, 4 * 16 * sizeof(float)>>>(x, W1l, b1l, xl1, NN, 16, 100, 0);
    k_linear<<<(NN + 3) / 4, T, 4 * 16 * sizeof(float)>>>(x, W1r, b1r, xr1, NN, 16, 100, 0);
    cudaMemsetAsync(m, 0, NN * sizeof(unsigned));
    cudaMemsetAsync(z, 0, NN * sizeof(float));
    k_score<<<edgeWarpGrid, T>>>(ei, ea, easum, deg, W1e, a1, xl1, xr1, s, m, 100);
    k_expz<<<(E2T + T - 1) / T, T>>>(ei, s, m, z);
    cudaMemsetAsync(out1, 0, (size_t)NN * 100 * sizeof(float));
    k_agg<<<edgeWarpGrid, T>>>(ei, s, z, xl1, out1, 100);
    k_bias_relu<<<(NN * 100 + T - 1) / T, T>>>(out1, c1, NN * 100, 100);

    // --- layer 2 (Cin=100 -> C=200) ---
    k_linear<<<(NN + 3) / 4, T, 4 * 100 * sizeof(float)>>>(out1, W2l, b2l, xl2, NN, 100, 200, 0);
    k_linear<<<(NN + 3) / 4, T, 4 * 100 * sizeof(float)>>>(out1, W2r, b2r, xr2, NN, 100, 200, 0);
    cudaMemsetAsync(m, 0, NN * sizeof(unsigned));
    cudaMemsetAsync(z, 0, NN * sizeof(float));
    k_score<<<edgeWarpGrid, T>>>(ei, ea, easum, deg, W2e, a2, xl2, xr2, s, m, 200);
    k_expz<<<(E2T + T - 1) / T, T>>>(ei, s, m, z);
    cudaMemsetAsync(out2, 0, (size_t)NN * 200 * sizeof(float));
    k_agg<<<edgeWarpGrid, T>>>(ei, s, z, xl2, out2, 200);
    k_bias_relu<<<(NN * 200 + T - 1) / T, T>>>(out2, c2, NN * 200, 200);

    // --- h3 = h2 @ W3 + b3 ---
    k_linear<<<(NN + 3) / 4, T, 4 * 200 * sizeof(float)>>>(out2, W3, b3, h3, NN, 200, 400, 0);

    // --- mean pool over graphs ---
    cudaMemsetAsync(pool, 0, GG * 400 * sizeof(float));
    cudaMemsetAsync(cnt, 0, GG * sizeof(float));
    k_pool<<<(NN * 400 + T - 1) / T, T>>>(h3, bid, pool, cnt);
    k_pooldiv<<<(GG * 400 + T - 1) / T, T>>>(pool, cnt);

    // --- FFN head ---
    k_linear<<<(GG + 3) / 4, T, 4 * 400 * sizeof(float)>>>(pool, F1, bf1, y1, GG, 400, 200, 1);
    k_linear<<<(GG + 3) / 4, T, 4 * 200 * sizeof(float)>>>(y1, F2, bf2, y2, GG, 200, 100, 1);
    k_linear<<<(GG + 3) / 4, T, 4 * 100 * sizeof(float)>>>(y2, F3, bf3, (float*)d_out, GG, 100, 100, 0);
}